// round 13
// baseline (speedup 1.0000x reference)
#include <cuda_runtime.h>

#define BB 512
#define NN 16384
#define H2 (0.0078125f * 0.0078125f)
#define THREADS 256
#define NWARP (THREADS / 32)
#define ITERS (NN / 4 / THREADS)       // 16 float4-groups per thread

__device__ float g_per_sample[BB];
__device__ unsigned int g_done_count = 0;      // wraps at BB-1

__device__ __forceinline__ float4 ldcs4(const float4* p) { return __ldcs(p); }

// H2 factored out; applied once at the end.
#define LANE(cc, P0, P1, P2, P3, TT) do {                                   \
    float ap0 = (cc) * (P0), ap1 = (cc) * (P1), ap2 = (cc) * (P2), ap3 = (cc) * (P3); \
    G[0] += ap0 * (P0);                                                     \
    G[1] += ap1 * (P0); G[2] += ap1 * (P1);                                 \
    G[3] += ap2 * (P0); G[4] += ap2 * (P1); G[5] += ap2 * (P2);             \
    G[6] += ap3 * (P0); G[7] += ap3 * (P1); G[8] += ap3 * (P2); G[9] += ap3 * (P3); \
    T[ 0] += ap0 * TT.x; T[ 1] += ap0 * TT.y; T[ 2] += ap0 * TT.z; T[ 3] += ap0 * TT.w; \
    T[ 4] += ap1 * TT.x; T[ 5] += ap1 * TT.y; T[ 6] += ap1 * TT.z; T[ 7] += ap1 * TT.w; \
    T[ 8] += ap2 * TT.x; T[ 9] += ap2 * TT.y; T[10] += ap2 * TT.z; T[11] += ap2 * TT.w; \
    T[12] += ap3 * TT.x; T[13] += ap3 * TT.y; T[14] += ap3 * TT.z; T[15] += ap3 * TT.w; \
} while (0)

__global__ __launch_bounds__(THREADS, 4)       // 64-reg budget -> 4 CTAs/SM -> all 512 resident
void loss_onewave_kernel(const float* __restrict__ coef,
                         const float* __restrict__ preds,
                         const float* __restrict__ targs,
                         float* __restrict__ out)
{
    const int b = blockIdx.x;

    const float* cb = coef  + (size_t)b * NN;
    const float* pb = preds + (size_t)b * 4 * NN;
    const float* tb = targs + (size_t)b * NN * 4;

    const float4* c4  = (const float4*)cb;
    const float4* p04 = (const float4*)(pb + 0 * NN);
    const float4* p14 = (const float4*)(pb + 1 * NN);
    const float4* p24 = (const float4*)(pb + 2 * NN);
    const float4* p34 = (const float4*)(pb + 3 * NN);
    const float4* t4  = (const float4*)tb;

    float G[10], T[16];
#pragma unroll
    for (int i = 0; i < 10; i++) G[i] = 0.f;
#pragma unroll
    for (int i = 0; i < 16; i++) T[i] = 0.f;

    const int tid = threadIdx.x;

#pragma unroll 1
    for (int k = 0; k < ITERS; k++) {
        const int n4 = k * THREADS + tid;
        // streaming (.cs) for the never-re-referenced unit-stride streams
        float4 cv = ldcs4(c4  + n4);
        float4 a0 = ldcs4(p04 + n4);
        float4 a1 = ldcs4(p14 + n4);
        float4 a2 = ldcs4(p24 + n4);
        float4 a3 = ldcs4(p34 + n4);
        // DEFAULT cache policy for targets: t0/t1 (t2/t3) pairs share 32B
        // sectors across lanes; evict-first risked duplicate DRAM fetches.
        float4 t0 = t4[n4 * 4 + 0];
        float4 t1 = t4[n4 * 4 + 1];
        float4 t2 = t4[n4 * 4 + 2];
        float4 t3 = t4[n4 * 4 + 3];

        LANE(cv.x, a0.x, a1.x, a2.x, a3.x, t0);
        LANE(cv.y, a0.y, a1.y, a2.y, a3.y, t1);
        LANE(cv.z, a0.z, a1.z, a2.z, a3.z, t2);
        LANE(cv.w, a0.w, a1.w, a2.w, a3.w, t3);
    }

    // ---- warp reduce 26 accumulators ----
#pragma unroll
    for (int i = 0; i < 10; i++) {
#pragma unroll
        for (int off = 16; off > 0; off >>= 1)
            G[i] += __shfl_down_sync(0xFFFFFFFFu, G[i], off);
    }
#pragma unroll
    for (int i = 0; i < 16; i++) {
#pragma unroll
        for (int off = 16; off > 0; off >>= 1)
            T[i] += __shfl_down_sync(0xFFFFFFFFu, T[i], off);
    }

    __shared__ float sred[26][NWARP];
    __shared__ float sacc[26];
    const int lid = tid & 31;
    const int wid = tid >> 5;
    if (lid == 0) {
#pragma unroll
        for (int i = 0; i < 10; i++) sred[i][wid] = G[i];
#pragma unroll
        for (int i = 0; i < 16; i++) sred[10 + i][wid] = T[i];
    }
    __syncthreads();

    // threads 0..25 each finish one accumulator (fixed order), parallel
    if (tid < 26) {
        float v = 0.f;
#pragma unroll
        for (int w = 0; w < NWARP; w++) v += sred[tid][w];
        sacc[tid] = v * H2;
    }
    __syncthreads();

    if (tid == 0) {
        float Gs[10], Ts[16];
#pragma unroll
        for (int i = 0; i < 10; i++) Gs[i] = sacc[i];
#pragma unroll
        for (int i = 0; i < 16; i++) Ts[i] = sacc[10 + i];

        float Gm[4][4];
        Gm[0][0] = Gs[0];
        Gm[1][0] = Gm[0][1] = Gs[1]; Gm[1][1] = Gs[2];
        Gm[2][0] = Gm[0][2] = Gs[3]; Gm[2][1] = Gm[1][2] = Gs[4]; Gm[2][2] = Gs[5];
        Gm[3][0] = Gm[0][3] = Gs[6]; Gm[3][1] = Gm[1][3] = Gs[7];
        Gm[3][2] = Gm[2][3] = Gs[8]; Gm[3][3] = Gs[9];

        float L[4][4];
#pragma unroll
        for (int j = 0; j < 4; j++) {
            float v[4] = {0.f, 0.f, 0.f, 0.f};
            v[j] = 1.f;
#pragma unroll
            for (int e = 0; e < 4; e++) {
                if (e >= j) break;
                float proj = 0.f;
#pragma unroll
                for (int k = 0; k < 4; k++) {
                    float gv = 0.f;
#pragma unroll
                    for (int l = 0; l < 4; l++) gv += Gm[k][l] * L[e][l];
                    proj += v[k] * gv;
                }
#pragma unroll
                for (int k = 0; k < 4; k++) v[k] -= proj * L[e][k];
            }
            float n2 = 0.f;
#pragma unroll
            for (int k = 0; k < 4; k++) {
                float gv = 0.f;
#pragma unroll
                for (int l = 0; l < 4; l++) gv += Gm[k][l] * v[l];
                n2 += v[k] * gv;
            }
            float sc = (n2 > 0.f) ? rsqrtf(n2) : 1.f;
#pragma unroll
            for (int k = 0; k < 4; k++) L[j][k] = v[k] * sc;
        }

        float ss = 0.f;
#pragma unroll
        for (int j = 0; j < 4; j++) {
#pragma unroll
            for (int m = 0; m < 4; m++) {
                float mv = 0.f;
#pragma unroll
                for (int k = 0; k < 4; k++) mv += L[j][k] * Ts[k * 4 + m];
                ss += mv * mv;
            }
        }
        g_per_sample[b] = (4.f - ss) * 0.25f;
    }

    // ---- deterministic fused finalize: last CTA reduces g_per_sample ----
    __shared__ bool s_is_last;
    __threadfence();
    __syncthreads();
    if (tid == 0) {
        unsigned int prev = atomicInc(&g_done_count, BB - 1);   // wraps -> replay-safe
        s_is_last = (prev == BB - 1);
    }
    __syncthreads();

    if (s_is_last) {
        __shared__ float sfin[THREADS];
        float v = __ldcg(&g_per_sample[tid]) + __ldcg(&g_per_sample[tid + THREADS]);
        sfin[tid] = v;
        __syncthreads();
#pragma unroll
        for (int off = THREADS / 2; off > 0; off >>= 1) {
            if (tid < off) sfin[tid] += sfin[tid + off];
            __syncthreads();
        }
        if (tid == 0) out[0] = sfin[0] * (1.f / (float)BB);
    }
}

extern "C" void kernel_launch(void* const* d_in, const int* in_sizes, int n_in,
                              void* d_out, int out_size)
{
    const float* coef  = (const float*)d_in[0];
    const float* preds = (const float*)d_in[1];
    const float* targs = (const float*)d_in[2];
    float* out = (float*)d_out;

    loss_onewave_kernel<<<BB, THREADS>>>(coef, preds, targs, out);
}

// round 14
// speedup vs baseline: 1.0150x; 1.0150x over previous
#include <cuda_runtime.h>

#define BB 512
#define NN 16384
#define H2 (0.0078125f * 0.0078125f)
#define THREADS 256
#define NWARP (THREADS / 32)
#define ITERS (NN / 4 / THREADS)       // 16 float4-groups per thread

__device__ float g_per_sample[BB];
__device__ unsigned int g_done_count = 0;      // wraps at BB-1

__device__ __forceinline__ float4 ldcs4(const float4* p) { return __ldcs(p); }

// H2 factored out; applied once at the end.
#define LANE(cc, P0, P1, P2, P3, TT) do {                                   \
    float ap0 = (cc) * (P0), ap1 = (cc) * (P1), ap2 = (cc) * (P2), ap3 = (cc) * (P3); \
    G[0] += ap0 * (P0);                                                     \
    G[1] += ap1 * (P0); G[2] += ap1 * (P1);                                 \
    G[3] += ap2 * (P0); G[4] += ap2 * (P1); G[5] += ap2 * (P2);             \
    G[6] += ap3 * (P0); G[7] += ap3 * (P1); G[8] += ap3 * (P2); G[9] += ap3 * (P3); \
    T[ 0] += ap0 * TT.x; T[ 1] += ap0 * TT.y; T[ 2] += ap0 * TT.z; T[ 3] += ap0 * TT.w; \
    T[ 4] += ap1 * TT.x; T[ 5] += ap1 * TT.y; T[ 6] += ap1 * TT.z; T[ 7] += ap1 * TT.w; \
    T[ 8] += ap2 * TT.x; T[ 9] += ap2 * TT.y; T[10] += ap2 * TT.z; T[11] += ap2 * TT.w; \
    T[12] += ap3 * TT.x; T[13] += ap3 * TT.y; T[14] += ap3 * TT.z; T[15] += ap3 * TT.w; \
} while (0)

__global__ __launch_bounds__(THREADS, 4)       // 64-reg budget -> 4 CTAs/SM -> all 512 resident
void loss_onewave_kernel(const float* __restrict__ coef,
                         const float* __restrict__ preds,
                         const float* __restrict__ targs,
                         float* __restrict__ out)
{
    const int b = blockIdx.x;

    const float* cb = coef  + (size_t)b * NN;
    const float* pb = preds + (size_t)b * 4 * NN;
    const float* tb = targs + (size_t)b * NN * 4;

    const float4* c4  = (const float4*)cb;
    const float4* p04 = (const float4*)(pb + 0 * NN);
    const float4* p14 = (const float4*)(pb + 1 * NN);
    const float4* p24 = (const float4*)(pb + 2 * NN);
    const float4* p34 = (const float4*)(pb + 3 * NN);
    const float4* t4  = (const float4*)tb;

    float G[10], T[16];
#pragma unroll
    for (int i = 0; i < 10; i++) G[i] = 0.f;
#pragma unroll
    for (int i = 0; i < 16; i++) T[i] = 0.f;

    const int tid = threadIdx.x;

#pragma unroll 1
    for (int k = 0; k < ITERS; k++) {
        const int n4 = k * THREADS + tid;
        float4 cv = ldcs4(c4  + n4);
        float4 a0 = ldcs4(p04 + n4);
        float4 a1 = ldcs4(p14 + n4);
        float4 a2 = ldcs4(p24 + n4);
        float4 a3 = ldcs4(p34 + n4);
        float4 t0 = ldcs4(t4 + n4 * 4 + 0);
        float4 t1 = ldcs4(t4 + n4 * 4 + 1);
        float4 t2 = ldcs4(t4 + n4 * 4 + 2);
        float4 t3 = ldcs4(t4 + n4 * 4 + 3);

        LANE(cv.x, a0.x, a1.x, a2.x, a3.x, t0);
        LANE(cv.y, a0.y, a1.y, a2.y, a3.y, t1);
        LANE(cv.z, a0.z, a1.z, a2.z, a3.z, t2);
        LANE(cv.w, a0.w, a1.w, a2.w, a3.w, t3);
    }

    // ---- warp reduce 26 accumulators ----
#pragma unroll
    for (int i = 0; i < 10; i++) {
#pragma unroll
        for (int off = 16; off > 0; off >>= 1)
            G[i] += __shfl_down_sync(0xFFFFFFFFu, G[i], off);
    }
#pragma unroll
    for (int i = 0; i < 16; i++) {
#pragma unroll
        for (int off = 16; off > 0; off >>= 1)
            T[i] += __shfl_down_sync(0xFFFFFFFFu, T[i], off);
    }

    __shared__ float sred[26][NWARP];
    __shared__ float sacc[26];
    const int lid = tid & 31;
    const int wid = tid >> 5;
    if (lid == 0) {
#pragma unroll
        for (int i = 0; i < 10; i++) sred[i][wid] = G[i];
#pragma unroll
        for (int i = 0; i < 16; i++) sred[10 + i][wid] = T[i];
    }
    __syncthreads();

    // threads 0..25 each finish one accumulator (fixed order), parallel
    if (tid < 26) {
        float v = 0.f;
#pragma unroll
        for (int w = 0; w < NWARP; w++) v += sred[tid][w];
        sacc[tid] = v * H2;
    }
    __syncthreads();

    if (tid == 0) {
        float Gs[10], Ts[16];
#pragma unroll
        for (int i = 0; i < 10; i++) Gs[i] = sacc[i];
#pragma unroll
        for (int i = 0; i < 16; i++) Ts[i] = sacc[10 + i];

        float Gm[4][4];
        Gm[0][0] = Gs[0];
        Gm[1][0] = Gm[0][1] = Gs[1]; Gm[1][1] = Gs[2];
        Gm[2][0] = Gm[0][2] = Gs[3]; Gm[2][1] = Gm[1][2] = Gs[4]; Gm[2][2] = Gs[5];
        Gm[3][0] = Gm[0][3] = Gs[6]; Gm[3][1] = Gm[1][3] = Gs[7];
        Gm[3][2] = Gm[2][3] = Gs[8]; Gm[3][3] = Gs[9];

        float L[4][4];
#pragma unroll
        for (int j = 0; j < 4; j++) {
            float v[4] = {0.f, 0.f, 0.f, 0.f};
            v[j] = 1.f;
#pragma unroll
            for (int e = 0; e < 4; e++) {
                if (e >= j) break;
                float proj = 0.f;
#pragma unroll
                for (int k = 0; k < 4; k++) {
                    float gv = 0.f;
#pragma unroll
                    for (int l = 0; l < 4; l++) gv += Gm[k][l] * L[e][l];
                    proj += v[k] * gv;
                }
#pragma unroll
                for (int k = 0; k < 4; k++) v[k] -= proj * L[e][k];
            }
            float n2 = 0.f;
#pragma unroll
            for (int k = 0; k < 4; k++) {
                float gv = 0.f;
#pragma unroll
                for (int l = 0; l < 4; l++) gv += Gm[k][l] * v[l];
                n2 += v[k] * gv;
            }
            float sc = (n2 > 0.f) ? rsqrtf(n2) : 1.f;
#pragma unroll
            for (int k = 0; k < 4; k++) L[j][k] = v[k] * sc;
        }

        float ss = 0.f;
#pragma unroll
        for (int j = 0; j < 4; j++) {
#pragma unroll
            for (int m = 0; m < 4; m++) {
                float mv = 0.f;
#pragma unroll
                for (int k = 0; k < 4; k++) mv += L[j][k] * Ts[k * 4 + m];
                ss += mv * mv;
            }
        }
        g_per_sample[b] = (4.f - ss) * 0.25f;
    }

    // ---- deterministic fused finalize: last CTA reduces g_per_sample ----
    __shared__ bool s_is_last;
    __threadfence();
    __syncthreads();
    if (tid == 0) {
        unsigned int prev = atomicInc(&g_done_count, BB - 1);   // wraps -> replay-safe
        s_is_last = (prev == BB - 1);
    }
    __syncthreads();

    if (s_is_last) {
        __shared__ float sfin[THREADS];
        float v = __ldcg(&g_per_sample[tid]) + __ldcg(&g_per_sample[tid + THREADS]);
        sfin[tid] = v;
        __syncthreads();
#pragma unroll
        for (int off = THREADS / 2; off > 0; off >>= 1) {
            if (tid < off) sfin[tid] += sfin[tid + off];
            __syncthreads();
        }
        if (tid == 0) out[0] = sfin[0] * (1.f / (float)BB);
    }
}

extern "C" void kernel_launch(void* const* d_in, const int* in_sizes, int n_in,
                              void* d_out, int out_size)
{
    const float* coef  = (const float*)d_in[0];
    const float* preds = (const float*)d_in[1];
    const float* targs = (const float*)d_in[2];
    float* out = (float*)d_out;

    loss_onewave_kernel<<<BB, THREADS>>>(coef, preds, targs, out);
}